// round 9
// baseline (speedup 1.0000x reference)
#include <cuda_runtime.h>
#include <cstdint>

// ---------------------------------------------------------------------------
// Inverse NTT over F_P, P = 2013265921 = 15*2^27 + 1, N = 2^22, C = 4.
// int32 inputs, float32 output (confirmed rel_err == 0).
//
// Two-phase NTT, radix-8/4 passes. Threads own uint2 half-rows (h = tid&1):
// 16 data regs -> 3 CTAs/SM. LDS.64 conflict-free via uint4-granule XOR
// swizzle + h-interleaved lanes. First R8 of phase 1 fused with the global
// gather; last R8 of both phases fused with the global store. 3 barriers/kernel.
// ---------------------------------------------------------------------------

#define LOGN 22
#define NN   (1u << LOGN)
#define NH   (1u << (LOGN - 1))

static constexpr unsigned int P        = 2013265921u;
static constexpr unsigned int PINV_NEG = 2013265919u;                  // -P^{-1} mod 2^32
static constexpr unsigned long long Rmod = (1ull << 32) % P;
static constexpr unsigned int R2C = (unsigned int)((Rmod * Rmod) % P); // 2^64 mod P

// Scratch, uint2 view: idx2 = idx4*2 + h, idx4 = ((v&1023)<<11 + b)*2 + (v>>10).
static __device__ uint2 g_scratch2[NN * 2];   // 64 MB

__device__ __forceinline__ unsigned int SZ(unsigned int p) {   // uint4-granule swizzle
    return p ^ ((p >> 3) & 7u);
}
__device__ __forceinline__ unsigned int mulmont(unsigned int a, unsigned int bR) {
    unsigned long long t = (unsigned long long)a * bR;
    unsigned int m = (unsigned int)t * PINV_NEG;
    unsigned long long s = t + (unsigned long long)m * P;
    unsigned int r = (unsigned int)(s >> 32);
    return (r >= P) ? r - P : r;
}
__device__ __forceinline__ unsigned int addmod(unsigned int a, unsigned int b) {
    unsigned int r = a + b;  return min(r, r - P);
}
__device__ __forceinline__ unsigned int submod(unsigned int a, unsigned int b) {
    unsigned int r = a - b;  return min(r, r + P);
}
__device__ __forceinline__ void bT(uint2& lo, uint2& hi, unsigned int T) {
    unsigned int t0 = mulmont(hi.x, T), t1 = mulmont(hi.y, T);
    uint2 l = lo;
    lo = make_uint2(addmod(l.x, t0), addmod(l.y, t1));
    hi = make_uint2(submod(l.x, t0), submod(l.y, t1));
}
__device__ __forceinline__ void b1(uint2& lo, uint2& hi) {
    uint2 l = lo, hh = hi;
    lo = make_uint2(addmod(l.x, hh.x), addmod(l.y, hh.y));
    hi = make_uint2(submod(l.x, hh.x), submod(l.y, hh.y));
}

// ---------------------------------------------------------------------------
// Phase 1: gather + stages 1..11 on 2048-slot tiles in bit-reversed storage.
// smem: tile j at uint2 offset j*4096 (entry = SZ(slot)*2 + h); shtw at 8192.
// ---------------------------------------------------------------------------
__global__ void __launch_bounds__(512, 3) k_stage1(const uint2* __restrict__ in2,
                                                   const unsigned int* __restrict__ tw) {
    extern __shared__ uint2 sm2[];
    unsigned int* shtw = (unsigned int*)(sm2 + 8192);
    const unsigned int t = threadIdx.x, h = t & 1u, m = t >> 1;   // m in [0,256)
    const unsigned int rb0 = 2u * blockIdx.x;

    shtw[t]        = mulmont(tw[(size_t)t << 11], R2C);
    shtw[t + 512u] = mulmont(tw[(size_t)(t + 512u) << 11], R2C);

    // R8a twiddles straight from gmem (shtw not yet visible)
    const unsigned int J  = mulmont(tw[1u << 20], R2C);
    const unsigned int K1 = mulmont(tw[1u << 19], R2C);
    const unsigned int K3 = mulmont(tw[3u << 19], R2C);

    uint2 x[8];
    // ---- fused gather + R8a: stages 1,2,3 (storage bits 10,9,8) ---------
    #pragma unroll
    for (int j = 0; j < 2; j++) {
        #pragma unroll
        for (int k = 0; k < 8; k++) {
            size_t row = ((size_t)(m + (k << 8)) << 11) | (rb0 + (unsigned)j);
            x[k] = in2[(row << 1) + h];
        }
        b1(x[0], x[4]); b1(x[1], x[5]); b1(x[2], x[6]); b1(x[3], x[7]);
        b1(x[0], x[2]); b1(x[1], x[3]); bT(x[4], x[6], J); bT(x[5], x[7], J);
        b1(x[0], x[1]); bT(x[2], x[3], J); bT(x[4], x[5], K1); bT(x[6], x[7], K3);
        #pragma unroll
        for (int k = 0; k < 8; k++)
            sm2[(j << 12) + (SZ(m + (k << 8)) << 1) + h] = x[k];
    }
    __syncthreads();

    // ---- R4: stages 4,5 (bits 7,6); quads {p0,+64,+128,+192} ------------
    #pragma unroll
    for (int j = 0; j < 2; j++) {
        #pragma unroll
        for (int r2 = 0; r2 < 2; r2++) {
            unsigned int q  = m + (r2 << 8);                 // [0,512)
            unsigned int lo = q & 63u, hi = q >> 6;
            unsigned int p0 = (hi << 8) | lo;
            unsigned int i  = (__brev(hi) >> 29) << 6;       // rev3(hi)<<6
            unsigned int T4 = shtw[i << 1], T5a = shtw[i], T5b = shtw[i + 512u];
            unsigned int b  = (j << 12) + h;
            uint2 x0 = sm2[b + (SZ(p0) << 1)];
            uint2 x1 = sm2[b + (SZ(p0 + 64u) << 1)];
            uint2 x2 = sm2[b + (SZ(p0 + 128u) << 1)];
            uint2 x3 = sm2[b + (SZ(p0 + 192u) << 1)];
            bT(x0, x2, T4);  bT(x1, x3, T4);                 // s=4 (diff 128)
            bT(x0, x1, T5a); bT(x2, x3, T5b);                // s=5 (diff 64)
            sm2[b + (SZ(p0) << 1)]        = x0;
            sm2[b + (SZ(p0 + 64u) << 1)]  = x1;
            sm2[b + (SZ(p0 + 128u) << 1)] = x2;
            sm2[b + (SZ(p0 + 192u) << 1)] = x3;
        }
    }
    __syncthreads();

    // ---- R8b: stages 6,7,8 (bits 5,4,3); slots vb + k*8 -----------------
    {
        const unsigned int lo3 = m & 7u, hi = m >> 3;        // hi < 32
        const unsigned int vb  = (hi << 6) | lo3;
        const unsigned int i   = (__brev(hi) >> 27) << 5;    // rev5(hi)<<5
        const unsigned int TA  = shtw[i];
        const unsigned int TB0 = shtw[i >> 1], TB1 = shtw[(i >> 1) + 512u];
        const unsigned int ib  = i >> 2;
        const unsigned int TC0 = shtw[ib],        TC1 = shtw[ib + 512u];
        const unsigned int TC2 = shtw[ib + 256u], TC3 = shtw[ib + 768u];
        #pragma unroll
        for (int j = 0; j < 2; j++) {
            unsigned int b = (j << 12) + h;
            #pragma unroll
            for (int k = 0; k < 8; k++) x[k] = sm2[b + (SZ(vb + (k << 3)) << 1)];
            bT(x[0], x[4], TA);  bT(x[1], x[5], TA);
            bT(x[2], x[6], TA);  bT(x[3], x[7], TA);
            bT(x[0], x[2], TB0); bT(x[1], x[3], TB0);
            bT(x[4], x[6], TB1); bT(x[5], x[7], TB1);
            bT(x[0], x[1], TC0); bT(x[2], x[3], TC1);
            bT(x[4], x[5], TC2); bT(x[6], x[7], TC3);
            #pragma unroll
            for (int k = 0; k < 8; k++) sm2[b + (SZ(vb + (k << 3)) << 1)] = x[k];
        }
    }
    __syncthreads();

    // ---- R8c: stages 9,10,11 (bits 2,1,0); slots 8m+k; fused store ------
    {
        const unsigned int i   = (__brev(m) >> 24) << 2;     // rev8(m)<<2
        const unsigned int TA  = shtw[i];
        const unsigned int TB0 = shtw[i >> 1], TB1 = shtw[(i >> 1) + 512u];
        const unsigned int ib  = i >> 2;
        const unsigned int TC0 = shtw[ib],        TC1 = shtw[ib + 512u];
        const unsigned int TC2 = shtw[ib + 256u], TC3 = shtw[ib + 768u];
        const unsigned int b0  = __brev(rb0) >> 21;          // < 1024
        const unsigned int mq  = m & 127u, hi10 = m >> 7;
        #pragma unroll
        for (int j = 0; j < 2; j++) {
            unsigned int b = (j << 12) + h;
            #pragma unroll
            for (int k = 0; k < 8; k++) x[k] = sm2[b + (SZ(8u * m + k) << 1)];
            bT(x[0], x[4], TA);  bT(x[1], x[5], TA);
            bT(x[2], x[6], TA);  bT(x[3], x[7], TA);
            bT(x[0], x[2], TB0); bT(x[1], x[3], TB0);
            bT(x[4], x[6], TB1); bT(x[5], x[7], TB1);
            bT(x[0], x[1], TC0); bT(x[2], x[3], TC1);
            bT(x[4], x[5], TC2); bT(x[6], x[7], TC3);
            unsigned int bj = b0 | ((unsigned)j << 10);
            #pragma unroll
            for (int k = 0; k < 8; k++) {
                size_t idx4 = ((((size_t)(8u * mq + k)) << 11) + bj) * 2 + hi10;
                g_scratch2[(idx4 << 1) + h] = x[k];
            }
        }
    }
}

// ---------------------------------------------------------------------------
// Phase 2: stages 12..22 as twisted natural-order 2048-NTT per column pair
// (tiles j=0,1 <-> columns C, C+1024 <-> output rows L0, L0+1), n_inv fused.
// Twist exp for slot s=8m+k: L*rev11(s) = L*rev8(m) + 256*L*rev3(k).
// ---------------------------------------------------------------------------
__global__ void __launch_bounds__(512, 3) k_stage2(float2* __restrict__ out2,
                                                   const unsigned int* __restrict__ tw,
                                                   const unsigned int* __restrict__ ni) {
    extern __shared__ uint2 sm2[];
    unsigned int* shtw = (unsigned int*)(sm2 + 8192);
    const unsigned int t = threadIdx.x, h = t & 1u, m = t >> 1;
    const unsigned int C  = blockIdx.x;
    const unsigned int L0 = __brev(C) >> 21;                 // even

    shtw[t]        = mulmont(tw[(size_t)t << 11], R2C);
    shtw[t + 512u] = mulmont(tw[(size_t)(t + 512u) << 11], R2C);

    const unsigned int J  = mulmont(tw[1u << 20], R2C);
    const unsigned int K1 = mulmont(tw[1u << 19], R2C);
    const unsigned int K3 = mulmont(tw[3u << 19], R2C);

    const unsigned int X   = mulmont(mulmont(ni[0], R2C), R2C);  // ninv * R^2
    const unsigned int r8m = __brev(m) >> 24;                    // rev8(m)

    uint2 x[8];
    // ---- fused scratch load + twist + R8a: sg 1,2,3 ---------------------
    #pragma unroll
    for (int j = 0; j < 2; j++) {
        const unsigned int Lj = L0 + (unsigned)j;
        #pragma unroll
        for (int k = 0; k < 8; k++) {
            size_t idx4 = ((((size_t)C << 11) + (8u * m + k)) << 1) + (unsigned)j;
            x[k] = g_scratch2[(idx4 << 1) + h];
        }
        const unsigned int Fb = mulmont(tw[Lj * r8m], X);    // exp < 2^19: no fold
        #pragma unroll
        for (int k = 0; k < 8; k++) {
            unsigned int r3 = __brev((unsigned)k) >> 29;     // rev3(k), compile-time
            unsigned int ek = (Lj * r3) << 8;                // < 2^22
            unsigned int w  = tw[ek & (NH - 1u)];
            if (ek & NH) w = P - w;                          // w^{-2^21} = -1
            unsigned int f  = mulmont(Fb, mulmont(w, R2C));
            x[k].x = mulmont(x[k].x, f);
            x[k].y = mulmont(x[k].y, f);
        }
        // R8a: sg1 (diff1), sg2 (diff2), sg3 (diff4)
        b1(x[0], x[1]); b1(x[2], x[3]); b1(x[4], x[5]); b1(x[6], x[7]);
        b1(x[0], x[2]); bT(x[1], x[3], J); b1(x[4], x[6]); bT(x[5], x[7], J);
        b1(x[0], x[4]); bT(x[1], x[5], K1); bT(x[2], x[6], J); bT(x[3], x[7], K3);
        #pragma unroll
        for (int k = 0; k < 8; k++)
            sm2[(j << 12) + (SZ(8u * m + k) << 1) + h] = x[k];
    }
    __syncthreads();

    // ---- R4: sg 4,5 (strides 8,16); quads {h0,+8,+16,+24} ---------------
    #pragma unroll
    for (int j = 0; j < 2; j++) {
        #pragma unroll
        for (int r2 = 0; r2 < 2; r2++) {
            unsigned int q   = m + (r2 << 8);
            unsigned int lo3 = q & 7u, hi = q >> 3;
            unsigned int h0  = (hi << 5) | lo3;
            unsigned int i   = lo3 << 6;
            unsigned int T4  = shtw[i << 1], T5a = shtw[i], T5b = shtw[i + 512u];
            unsigned int b   = (j << 12) + h;
            uint2 x0 = sm2[b + (SZ(h0) << 1)];
            uint2 x1 = sm2[b + (SZ(h0 + 8u) << 1)];
            uint2 x2 = sm2[b + (SZ(h0 + 16u) << 1)];
            uint2 x3 = sm2[b + (SZ(h0 + 24u) << 1)];
            bT(x0, x1, T4);  bT(x2, x3, T4);                 // sg=4
            bT(x0, x2, T5a); bT(x1, x3, T5b);                // sg=5
            sm2[b + (SZ(h0) << 1)]        = x0;
            sm2[b + (SZ(h0 + 8u) << 1)]   = x1;
            sm2[b + (SZ(h0 + 16u) << 1)]  = x2;
            sm2[b + (SZ(h0 + 24u) << 1)]  = x3;
        }
    }
    __syncthreads();

    // ---- R8b: sg 6,7,8 (strides 32,64,128); slots vb + k*32 -------------
    {
        const unsigned int lo5 = m & 31u, hi = m >> 5;       // hi < 8
        const unsigned int vb  = (hi << 8) | lo5;
        const unsigned int i   = lo5 << 5;
        const unsigned int TA  = shtw[i];
        const unsigned int TB0 = shtw[i >> 1], TB1 = shtw[(i >> 1) + 512u];
        const unsigned int ib  = i >> 2;
        const unsigned int TC0 = shtw[ib],        TC1 = shtw[ib + 256u];
        const unsigned int TC2 = shtw[ib + 512u], TC3 = shtw[ib + 768u];
        #pragma unroll
        for (int j = 0; j < 2; j++) {
            unsigned int b = (j << 12) + h;
            #pragma unroll
            for (int k = 0; k < 8; k++) x[k] = sm2[b + (SZ(vb + (k << 5)) << 1)];
            bT(x[0], x[1], TA);  bT(x[2], x[3], TA);
            bT(x[4], x[5], TA);  bT(x[6], x[7], TA);
            bT(x[0], x[2], TB0); bT(x[1], x[3], TB1);
            bT(x[4], x[6], TB0); bT(x[5], x[7], TB1);
            bT(x[0], x[4], TC0); bT(x[1], x[5], TC1);
            bT(x[2], x[6], TC2); bT(x[3], x[7], TC3);
            #pragma unroll
            for (int k = 0; k < 8; k++) sm2[b + (SZ(vb + (k << 5)) << 1)] = x[k];
        }
    }
    __syncthreads();

    // ---- R8c: sg 9,10,11 (strides 256,512,1024); slots k*256+m; fused out
    {
        const unsigned int i   = m << 2;
        const unsigned int TA  = shtw[i];
        const unsigned int TB0 = shtw[i >> 1], TB1 = shtw[(i >> 1) + 512u];
        const unsigned int TC0 = shtw[m],        TC1 = shtw[m + 256u];
        const unsigned int TC2 = shtw[m + 512u], TC3 = shtw[m + 768u];
        #pragma unroll
        for (int j = 0; j < 2; j++) {
            unsigned int b = (j << 12) + h;
            #pragma unroll
            for (int k = 0; k < 8; k++) x[k] = sm2[b + (SZ((k << 8) + m) << 1)];
            bT(x[0], x[1], TA);  bT(x[2], x[3], TA);
            bT(x[4], x[5], TA);  bT(x[6], x[7], TA);
            bT(x[0], x[2], TB0); bT(x[1], x[3], TB1);
            bT(x[4], x[6], TB0); bT(x[5], x[7], TB1);
            bT(x[0], x[4], TC0); bT(x[1], x[5], TC1);
            bT(x[2], x[6], TC2); bT(x[3], x[7], TC3);
            #pragma unroll
            for (int k = 0; k < 8; k++) {
                size_t row4 = (((size_t)((k << 8) + m)) << 11) | (L0 + (unsigned)j);
                out2[(row4 << 1) + h] = make_float2((float)x[k].x, (float)x[k].y);
            }
        }
    }
}

// ---------------------------------------------------------------------------

extern "C" void kernel_launch(void* const* d_in, const int* in_sizes, int n_in,
                              void* d_out, int out_size) {
    const void* p_in = (n_in > 0) ? d_in[0] : nullptr;
    const void* p_tw = (n_in > 1) ? d_in[1] : nullptr;
    const void* p_ni = (n_in > 2) ? d_in[2] : nullptr;
    for (int i = 0; i < n_in; i++) {
        unsigned int sz = (unsigned int)in_sizes[i];
        if (sz == NN * 4u) p_in = d_in[i];
        else if (sz == NH) p_tw = d_in[i];
        else if (sz == 1u) p_ni = d_in[i];
    }

    const int smem = 8192 * (int)sizeof(uint2) + 1024 * (int)sizeof(unsigned int); // 69632
    cudaFuncSetAttribute(k_stage1, cudaFuncAttributeMaxDynamicSharedMemorySize, smem);
    cudaFuncSetAttribute(k_stage2, cudaFuncAttributeMaxDynamicSharedMemorySize, smem);

    k_stage1<<< 1024, 512, smem >>>((const uint2*)p_in, (const unsigned int*)p_tw);
    k_stage2<<< 1024, 512, smem >>>((float2*)d_out, (const unsigned int*)p_tw,
                                    (const unsigned int*)p_ni);
    (void)out_size;
}

// round 10
// speedup vs baseline: 1.4403x; 1.4403x over previous
#include <cuda_runtime.h>
#include <cstdint>

// ---------------------------------------------------------------------------
// Inverse NTT over F_P, P = 2013265921 = 15*2^27 + 1, N = 2^22, C = 4.
// int32 inputs, float32 output (confirmed rel_err == 0).
//
// Two-phase NTT, radix-8/4 passes in swizzled shared memory (uint4 lanes):
//   phase 1: fused gather+R8 | R4 | R8 | fused R8+scratch-store   (3 syncs)
//   phase 2: fused load+twist+R8 | R4 | R8 | fused R8+output      (3 syncs)
// Stage twiddles: 1024-entry decimated set tw[k<<11], staged in shared and
// Montgomery-converted on the fly.  Four-step twist carries n_inv.
// ---------------------------------------------------------------------------

#define LOGN 22
#define NN   (1u << LOGN)
#define NH   (1u << (LOGN - 1))

static constexpr unsigned int P        = 2013265921u;
static constexpr unsigned int PINV_NEG = 2013265919u;                  // -P^{-1} mod 2^32
static constexpr unsigned long long Rmod = (1ull << 32) % P;
static constexpr unsigned int R2C = (unsigned int)((Rmod * Rmod) % P); // 2^64 mod P

// Scratch: phase-1 tile-row b, slot v at ((v&1023)<<11 + b)*2 + (v>>10).
static __device__ uint4 g_scratch[NN];   // 64 MB

__device__ __forceinline__ unsigned int SZ(unsigned int p) {
    return p ^ ((p >> 3) & 7u);
}
__device__ __forceinline__ unsigned int mulmont(unsigned int a, unsigned int bR) {
    unsigned long long t = (unsigned long long)a * bR;
    unsigned int m = (unsigned int)t * PINV_NEG;
    unsigned long long s = t + (unsigned long long)m * P;
    unsigned int r = (unsigned int)(s >> 32);
    return (r >= P) ? r - P : r;
}
__device__ __forceinline__ unsigned int addmod(unsigned int a, unsigned int b) {
    unsigned int r = a + b;  return min(r, r - P);
}
__device__ __forceinline__ unsigned int submod(unsigned int a, unsigned int b) {
    unsigned int r = a - b;  return min(r, r + P);
}
__device__ __forceinline__ void bflyT(uint4& lo, uint4& hi, unsigned int T) {
    unsigned int t0 = mulmont(hi.x, T), t1 = mulmont(hi.y, T);
    unsigned int t2 = mulmont(hi.z, T), t3 = mulmont(hi.w, T);
    uint4 l = lo;
    lo = make_uint4(addmod(l.x, t0), addmod(l.y, t1), addmod(l.z, t2), addmod(l.w, t3));
    hi = make_uint4(submod(l.x, t0), submod(l.y, t1), submod(l.z, t2), submod(l.w, t3));
}
__device__ __forceinline__ void bfly1(uint4& lo, uint4& hi) {
    uint4 l = lo, h = hi;
    lo = make_uint4(addmod(l.x, h.x), addmod(l.y, h.y), addmod(l.z, h.z), addmod(l.w, h.w));
    hi = make_uint4(submod(l.x, h.x), submod(l.y, h.y), submod(l.z, h.z), submod(l.w, h.w));
}

// ---------------------------------------------------------------------------
// Phase 1: gather + stages 1..11 on 2048-slot tiles in bit-reversed storage.
// Thread-half jt = tid>>8 owns gather residue rb0+jt (tile jt), m = tid&255.
// ---------------------------------------------------------------------------
__global__ void __launch_bounds__(512) k_stage1(const uint4* __restrict__ in,
                                                const unsigned int* __restrict__ tw) {
    extern __shared__ uint4 smem[];                 // 2 tiles of 2048 + shtw
    unsigned int* shtw = (unsigned int*)(smem + 4096);

    const unsigned int tid = threadIdx.x;
    const unsigned int rb0 = 2u * blockIdx.x;
    const unsigned int jt  = tid >> 8, m = tid & 255u;
    const unsigned int tb  = jt << 11;

    shtw[tid]        = mulmont(tw[(size_t)tid << 11], R2C);
    shtw[tid + 512u] = mulmont(tw[(size_t)(tid + 512u) << 11], R2C);

    // R8a twiddles straight from gmem (pre-barrier)
    const unsigned int J  = mulmont(tw[1u << 20], R2C);
    const unsigned int K1 = mulmont(tw[1u << 19], R2C);
    const unsigned int K3 = mulmont(tw[3u << 19], R2C);

    uint4 x[8];
    // ---- fused gather + R8a: stages 1,2,3 (storage bits 10,9,8) ---------
    #pragma unroll
    for (int k = 0; k < 8; k++)
        x[k] = in[((size_t)(m + (k << 8)) << 11) | (rb0 + jt)];
    bfly1(x[0], x[4]); bfly1(x[1], x[5]); bfly1(x[2], x[6]); bfly1(x[3], x[7]);
    bfly1(x[0], x[2]); bfly1(x[1], x[3]);
    bflyT(x[4], x[6], J); bflyT(x[5], x[7], J);
    bfly1(x[0], x[1]); bflyT(x[2], x[3], J);
    bflyT(x[4], x[5], K1); bflyT(x[6], x[7], K3);
    #pragma unroll
    for (int k = 0; k < 8; k++) smem[tb + SZ(m + (k << 8))] = x[k];
    __syncthreads();

    // ---- R4: stages 4,5 (bits 7,6); quads {p0,+64,+128,+192} ------------
    {
        const unsigned int lo = tid & 63u, hi = tid >> 6;      // hi < 8
        const unsigned int p0 = (hi << 8) | lo;
        const unsigned int i  = (__brev(hi) >> 29) << 6;       // rev3(hi)<<6
        const unsigned int T4 = shtw[i << 1], T5a = shtw[i], T5b = shtw[i + 512u];
        #pragma unroll
        for (int t = 0; t < 2; t++) {
            const unsigned int b = t << 11;
            uint4 x0 = smem[b + SZ(p0)],        x1 = smem[b + SZ(p0 + 64u)];
            uint4 x2 = smem[b + SZ(p0 + 128u)], x3 = smem[b + SZ(p0 + 192u)];
            bflyT(x0, x2, T4); bflyT(x1, x3, T4);              // s=4 (diff 128)
            bflyT(x0, x1, T5a); bflyT(x2, x3, T5b);            // s=5 (diff 64)
            smem[b + SZ(p0)] = x0;        smem[b + SZ(p0 + 64u)]  = x1;
            smem[b + SZ(p0 + 128u)] = x2; smem[b + SZ(p0 + 192u)] = x3;
        }
    }
    __syncthreads();

    // ---- R8b: stages 6,7,8 (bits 5,4,3); slots vb + k*8 -----------------
    {
        const unsigned int lo3 = m & 7u, hi = m >> 3;          // hi < 32
        const unsigned int vb  = (hi << 6) | lo3;
        #pragma unroll
        for (int k = 0; k < 8; k++) x[k] = smem[tb + SZ(vb + (k << 3))];
        const unsigned int i   = (__brev(hi) >> 27) << 5;      // rev5(hi)<<5
        const unsigned int TA  = shtw[i];
        const unsigned int TB0 = shtw[i >> 1], TB1 = shtw[(i >> 1) + 512u];
        const unsigned int ib  = i >> 2;
        const unsigned int TC0 = shtw[ib],        TC1 = shtw[ib + 512u];
        const unsigned int TC2 = shtw[ib + 256u], TC3 = shtw[ib + 768u];
        bflyT(x[0], x[4], TA); bflyT(x[1], x[5], TA);
        bflyT(x[2], x[6], TA); bflyT(x[3], x[7], TA);
        bflyT(x[0], x[2], TB0); bflyT(x[1], x[3], TB0);
        bflyT(x[4], x[6], TB1); bflyT(x[5], x[7], TB1);
        bflyT(x[0], x[1], TC0); bflyT(x[2], x[3], TC1);
        bflyT(x[4], x[5], TC2); bflyT(x[6], x[7], TC3);
        #pragma unroll
        for (int k = 0; k < 8; k++) smem[tb + SZ(vb + (k << 3))] = x[k];
    }
    __syncthreads();

    // ---- R8c: stages 9,10,11 (bits 2,1,0); slots 8m+k; fused store ------
    {
        #pragma unroll
        for (int k = 0; k < 8; k++) x[k] = smem[tb + SZ(8u * m + k)];
        const unsigned int i   = (__brev(m) >> 24) << 2;       // rev8(m)<<2
        const unsigned int TA  = shtw[i];
        const unsigned int TB0 = shtw[i >> 1], TB1 = shtw[(i >> 1) + 512u];
        const unsigned int ib  = i >> 2;
        const unsigned int TC0 = shtw[ib],        TC1 = shtw[ib + 512u];
        const unsigned int TC2 = shtw[ib + 256u], TC3 = shtw[ib + 768u];
        bflyT(x[0], x[4], TA); bflyT(x[1], x[5], TA);
        bflyT(x[2], x[6], TA); bflyT(x[3], x[7], TA);
        bflyT(x[0], x[2], TB0); bflyT(x[1], x[3], TB0);
        bflyT(x[4], x[6], TB1); bflyT(x[5], x[7], TB1);
        bflyT(x[0], x[1], TC0); bflyT(x[2], x[3], TC1);
        bflyT(x[4], x[5], TC2); bflyT(x[6], x[7], TC3);

        const unsigned int b0  = __brev(rb0) >> 21;            // < 1024
        const unsigned int bj  = b0 | (jt << 10);
        const unsigned int mq  = m & 127u, bit10 = m >> 7;     // (8m+k)>>10
        #pragma unroll
        for (int k = 0; k < 8; k++)
            g_scratch[((((size_t)(8u * mq + k)) << 11) + bj) * 2 + bit10] = x[k];
    }
}

// ---------------------------------------------------------------------------
// Phase 2: stages 12..22 as twisted natural-order 2048-NTT per column.
// Thread-half j = tid>>8 owns column C + j*1024 (L = rev11(C)+j), m = tid&255.
// Twist for slot s = 8m+k:  w^{-L*rev11(s)} * n_inv,
//   rev11(s) = rev8(m) + 256*rev3(k)  ->  Fb * W^{rev3(k)}, W = mont(w^{-256L}).
// ---------------------------------------------------------------------------
__global__ void __launch_bounds__(512) k_stage2(float4* __restrict__ out,
                                                const unsigned int* __restrict__ tw,
                                                const unsigned int* __restrict__ ni) {
    extern __shared__ uint4 smem[];
    unsigned int* shtw = (unsigned int*)(smem + 4096);

    const unsigned int tid = threadIdx.x;
    const unsigned int C   = blockIdx.x;
    const unsigned int L0  = __brev(C) >> 21;      // even
    const unsigned int j   = tid >> 8, m = tid & 255u;
    const unsigned int tb  = j << 11;
    const unsigned int L   = L0 + j;

    shtw[tid]        = mulmont(tw[(size_t)tid << 11], R2C);
    shtw[tid + 512u] = mulmont(tw[(size_t)(tid + 512u) << 11], R2C);

    const unsigned int J  = mulmont(tw[1u << 20], R2C);
    const unsigned int K1 = mulmont(tw[1u << 19], R2C);
    const unsigned int K3 = mulmont(tw[3u << 19], R2C);

    uint4 x[8];
    // ---- fused scratch load + twist + R8a: sg 1,2,3 ---------------------
    {
        #pragma unroll
        for (int k = 0; k < 8; k++)
            x[k] = g_scratch[((((size_t)C << 11) + (8u * m + k))) * 2 + j];

        const unsigned int X   = mulmont(mulmont(ni[0], R2C), R2C); // ninv * R^2
        const unsigned int r8m = __brev(m) >> 24;                   // rev8(m)
        const unsigned int Fb  = mulmont(tw[L * r8m], X);           // exp < 2^20
        const unsigned int W1  = mulmont(tw[L << 8], R2C);          // exp < 2^21
        const unsigned int W2  = mulmont(W1, W1);
        const unsigned int W3  = mulmont(W2, W1);
        const unsigned int W4  = mulmont(W2, W2);
        const unsigned int W5  = mulmont(W4, W1);
        const unsigned int W6  = mulmont(W3, W3);
        const unsigned int W7  = mulmont(W4, W3);
        unsigned int F[8];                                          // Fb * W^{rev3(k)}
        F[0] = Fb;              F[1] = mulmont(Fb, W4);
        F[2] = mulmont(Fb, W2); F[3] = mulmont(Fb, W6);
        F[4] = mulmont(Fb, W1); F[5] = mulmont(Fb, W5);
        F[6] = mulmont(Fb, W3); F[7] = mulmont(Fb, W7);
        #pragma unroll
        for (int k = 0; k < 8; k++) {
            x[k].x = mulmont(x[k].x, F[k]); x[k].y = mulmont(x[k].y, F[k]);
            x[k].z = mulmont(x[k].z, F[k]); x[k].w = mulmont(x[k].w, F[k]);
        }
        // R8a: sg1 (diff 1), sg2 (diff 2), sg3 (diff 4)
        bfly1(x[0], x[1]); bfly1(x[2], x[3]); bfly1(x[4], x[5]); bfly1(x[6], x[7]);
        bfly1(x[0], x[2]); bflyT(x[1], x[3], J);
        bfly1(x[4], x[6]); bflyT(x[5], x[7], J);
        bfly1(x[0], x[4]); bflyT(x[1], x[5], K1);
        bflyT(x[2], x[6], J); bflyT(x[3], x[7], K3);
        #pragma unroll
        for (int k = 0; k < 8; k++) smem[tb + SZ(8u * m + k)] = x[k];
    }
    __syncthreads();

    // ---- R4: sg 4,5 (strides 8,16); quads {h0,+8,+16,+24} ---------------
    {
        const unsigned int lo3 = tid & 7u, hi = tid >> 3;      // hi < 64
        const unsigned int h0  = (hi << 5) | lo3;
        const unsigned int i   = lo3 << 6;
        const unsigned int T4 = shtw[i << 1], T5a = shtw[i], T5b = shtw[i + 512u];
        #pragma unroll
        for (int t = 0; t < 2; t++) {
            const unsigned int b = t << 11;
            uint4 x0 = smem[b + SZ(h0)],        x1 = smem[b + SZ(h0 + 8u)];
            uint4 x2 = smem[b + SZ(h0 + 16u)],  x3 = smem[b + SZ(h0 + 24u)];
            bflyT(x0, x1, T4); bflyT(x2, x3, T4);              // sg=4
            bflyT(x0, x2, T5a); bflyT(x1, x3, T5b);            // sg=5
            smem[b + SZ(h0)] = x0;        smem[b + SZ(h0 + 8u)]  = x1;
            smem[b + SZ(h0 + 16u)] = x2;  smem[b + SZ(h0 + 24u)] = x3;
        }
    }
    __syncthreads();

    // ---- R8b: sg 6,7,8 (strides 32,64,128); slots vb + k*32 -------------
    {
        const unsigned int lo5 = m & 31u, hi = m >> 5;         // hi < 8
        const unsigned int vb  = (hi << 8) | lo5;
        #pragma unroll
        for (int k = 0; k < 8; k++) x[k] = smem[tb + SZ(vb + (k << 5))];
        const unsigned int i   = lo5 << 5;
        const unsigned int TA  = shtw[i];
        const unsigned int TB0 = shtw[i >> 1], TB1 = shtw[(i >> 1) + 512u];
        const unsigned int ib  = i >> 2;
        const unsigned int TC0 = shtw[ib],        TC1 = shtw[ib + 256u];
        const unsigned int TC2 = shtw[ib + 512u], TC3 = shtw[ib + 768u];
        bflyT(x[0], x[1], TA); bflyT(x[2], x[3], TA);
        bflyT(x[4], x[5], TA); bflyT(x[6], x[7], TA);
        bflyT(x[0], x[2], TB0); bflyT(x[1], x[3], TB1);
        bflyT(x[4], x[6], TB0); bflyT(x[5], x[7], TB1);
        bflyT(x[0], x[4], TC0); bflyT(x[1], x[5], TC1);
        bflyT(x[2], x[6], TC2); bflyT(x[3], x[7], TC3);
        #pragma unroll
        for (int k = 0; k < 8; k++) smem[tb + SZ(vb + (k << 5))] = x[k];
    }
    __syncthreads();

    // ---- R8c: sg 9,10,11 (strides 256,512,1024); slots k*256+m; fused out
    {
        #pragma unroll
        for (int k = 0; k < 8; k++) x[k] = smem[tb + SZ((k << 8) + m)];
        const unsigned int i   = m << 2;
        const unsigned int TA  = shtw[i];
        const unsigned int TB0 = shtw[i >> 1], TB1 = shtw[(i >> 1) + 512u];
        const unsigned int TC0 = shtw[m],        TC1 = shtw[m + 256u];
        const unsigned int TC2 = shtw[m + 512u], TC3 = shtw[m + 768u];
        bflyT(x[0], x[1], TA); bflyT(x[2], x[3], TA);
        bflyT(x[4], x[5], TA); bflyT(x[6], x[7], TA);
        bflyT(x[0], x[2], TB0); bflyT(x[1], x[3], TB1);
        bflyT(x[4], x[6], TB0); bflyT(x[5], x[7], TB1);
        bflyT(x[0], x[4], TC0); bflyT(x[1], x[5], TC1);
        bflyT(x[2], x[6], TC2); bflyT(x[3], x[7], TC3);
        #pragma unroll
        for (int k = 0; k < 8; k++) {
            size_t row = (((size_t)((k << 8) + m)) << 11) | L;
            out[row] = make_float4((float)x[k].x, (float)x[k].y,
                                   (float)x[k].z, (float)x[k].w);
        }
    }
}

// ---------------------------------------------------------------------------

extern "C" void kernel_launch(void* const* d_in, const int* in_sizes, int n_in,
                              void* d_out, int out_size) {
    const void* p_in = (n_in > 0) ? d_in[0] : nullptr;
    const void* p_tw = (n_in > 1) ? d_in[1] : nullptr;
    const void* p_ni = (n_in > 2) ? d_in[2] : nullptr;
    for (int i = 0; i < n_in; i++) {
        unsigned int sz = (unsigned int)in_sizes[i];
        if (sz == NN * 4u) p_in = d_in[i];
        else if (sz == NH) p_tw = d_in[i];
        else if (sz == 1u) p_ni = d_in[i];
    }

    const int smem = 4096 * (int)sizeof(uint4) + 1024 * (int)sizeof(unsigned int); // 69632
    cudaFuncSetAttribute(k_stage1, cudaFuncAttributeMaxDynamicSharedMemorySize, smem);
    cudaFuncSetAttribute(k_stage2, cudaFuncAttributeMaxDynamicSharedMemorySize, smem);

    k_stage1<<< 1024, 512, smem >>>((const uint4*)p_in, (const unsigned int*)p_tw);
    k_stage2<<< 1024, 512, smem >>>((float4*)d_out, (const unsigned int*)p_tw,
                                    (const unsigned int*)p_ni);
    (void)out_size;
}

// round 11
// speedup vs baseline: 1.4602x; 1.0138x over previous
#include <cuda_runtime.h>
#include <cstdint>

// ---------------------------------------------------------------------------
// Inverse NTT over F_P, P = 2013265921 = 15*2^27 + 1, N = 2^22, C = 4.
// int32 inputs, float32 output (confirmed rel_err == 0).
//
// Two-phase NTT, radix-8/4 passes in swizzled shared memory (uint4 lanes).
// Each block = two independent 2048-pt tiles; middle passes synchronize each
// 256-thread half with its own named barrier (halves overlap each other's
// latency bursts).  Memory seams keep full 32B sectors (R8 structure).
//   phase 1: staged gather | R8 | R4 | R8 | R8 | staged scratch store
//   phase 2: prefetched load+twist+R8 | R4 | R8 | fused R8+output
// ---------------------------------------------------------------------------

#define LOGN 22
#define NN   (1u << LOGN)
#define NH   (1u << (LOGN - 1))

static constexpr unsigned int P        = 2013265921u;
static constexpr unsigned int PINV_NEG = 2013265919u;                  // -P^{-1} mod 2^32
static constexpr unsigned long long Rmod = (1ull << 32) % P;
static constexpr unsigned int R2C = (unsigned int)((Rmod * Rmod) % P); // 2^64 mod P

// Scratch: phase-1 tile-row b, slot v at ((v&1023)<<11 + b)*2 + (v>>10).
static __device__ uint4 g_scratch[NN];   // 64 MB

__device__ __forceinline__ void barhalf(unsigned int id) {
    asm volatile("bar.sync %0, %1;" :: "r"(id), "r"(256u) : "memory");
}
__device__ __forceinline__ unsigned int SZ(unsigned int p) {
    return p ^ ((p >> 3) & 7u);
}
__device__ __forceinline__ unsigned int mulmont(unsigned int a, unsigned int bR) {
    unsigned long long t = (unsigned long long)a * bR;
    unsigned int m = (unsigned int)t * PINV_NEG;
    unsigned long long s = t + (unsigned long long)m * P;
    unsigned int r = (unsigned int)(s >> 32);
    return (r >= P) ? r - P : r;
}
__device__ __forceinline__ unsigned int addmod(unsigned int a, unsigned int b) {
    unsigned int r = a + b;  return min(r, r - P);
}
__device__ __forceinline__ unsigned int submod(unsigned int a, unsigned int b) {
    unsigned int r = a - b;  return min(r, r + P);
}
__device__ __forceinline__ void bflyT(uint4& lo, uint4& hi, unsigned int T) {
    unsigned int t0 = mulmont(hi.x, T), t1 = mulmont(hi.y, T);
    unsigned int t2 = mulmont(hi.z, T), t3 = mulmont(hi.w, T);
    uint4 l = lo;
    lo = make_uint4(addmod(l.x, t0), addmod(l.y, t1), addmod(l.z, t2), addmod(l.w, t3));
    hi = make_uint4(submod(l.x, t0), submod(l.y, t1), submod(l.z, t2), submod(l.w, t3));
}
__device__ __forceinline__ void bfly1(uint4& lo, uint4& hi) {
    uint4 l = lo, h = hi;
    lo = make_uint4(addmod(l.x, h.x), addmod(l.y, h.y), addmod(l.z, h.z), addmod(l.w, h.w));
    hi = make_uint4(submod(l.x, h.x), submod(l.y, h.y), submod(l.z, h.z), submod(l.w, h.w));
}

// ---------------------------------------------------------------------------
// Phase 1: gather + stages 1..11 on 2048-slot tiles in bit-reversed storage.
// ---------------------------------------------------------------------------
__global__ void __launch_bounds__(512) k_stage1(const uint4* __restrict__ in,
                                                const unsigned int* __restrict__ tw) {
    extern __shared__ uint4 smem[];                 // 2 tiles of 2048 + shtw
    unsigned int* shtw = (unsigned int*)(smem + 4096);

    const unsigned int tid = threadIdx.x;
    const unsigned int rb0 = 2u * blockIdx.x;
    const unsigned int jt  = tid >> 8, m = tid & 255u;
    const unsigned int tb  = jt << 11;
    const unsigned int BAR = 1u + jt;

    shtw[tid]        = mulmont(tw[(size_t)tid << 11], R2C);
    shtw[tid + 512u] = mulmont(tw[(size_t)(tid + 512u) << 11], R2C);

    // staged gather: 32B per thread-row (both tiles)
    #pragma unroll
    for (int r = 0; r < 4; r++) {
        unsigned int p = tid + r * 512u;
        size_t row = ((size_t)p << 11) | rb0;
        smem[SZ(p)]         = in[row];
        smem[2048u + SZ(p)] = in[row + 1];
    }
    __syncthreads();

    uint4 x[8];
    // ---- R8a: stages 1,2,3 (bits 10,9,8); slots m + k*256 ---------------
    {
        #pragma unroll
        for (int k = 0; k < 8; k++) x[k] = smem[tb + SZ(m + (k << 8))];
        const unsigned int J  = shtw[512], K1 = shtw[256], K3 = shtw[768];
        bfly1(x[0], x[4]); bfly1(x[1], x[5]); bfly1(x[2], x[6]); bfly1(x[3], x[7]);
        bfly1(x[0], x[2]); bfly1(x[1], x[3]);
        bflyT(x[4], x[6], J); bflyT(x[5], x[7], J);
        bfly1(x[0], x[1]); bflyT(x[2], x[3], J);
        bflyT(x[4], x[5], K1); bflyT(x[6], x[7], K3);
        #pragma unroll
        for (int k = 0; k < 8; k++) smem[tb + SZ(m + (k << 8))] = x[k];
    }
    barhalf(BAR);

    // ---- R4: stages 4,5 (bits 7,6); half-local: quads q = m, m+256 ------
    #pragma unroll
    for (int r2 = 0; r2 < 2; r2++) {
        unsigned int q  = m + ((unsigned)r2 << 8);        // [0,512)
        unsigned int lo = q & 63u, hi = q >> 6;           // hi < 8
        unsigned int p0 = (hi << 8) | lo;
        unsigned int i  = (__brev(hi) >> 29) << 6;        // rev3(hi)<<6
        unsigned int T4 = shtw[i << 1], T5a = shtw[i], T5b = shtw[i + 512u];
        uint4 x0 = smem[tb + SZ(p0)],        x1 = smem[tb + SZ(p0 + 64u)];
        uint4 x2 = smem[tb + SZ(p0 + 128u)], x3 = smem[tb + SZ(p0 + 192u)];
        bflyT(x0, x2, T4); bflyT(x1, x3, T4);             // s=4 (diff 128)
        bflyT(x0, x1, T5a); bflyT(x2, x3, T5b);           // s=5 (diff 64)
        smem[tb + SZ(p0)] = x0;        smem[tb + SZ(p0 + 64u)]  = x1;
        smem[tb + SZ(p0 + 128u)] = x2; smem[tb + SZ(p0 + 192u)] = x3;
    }
    barhalf(BAR);

    // ---- R8b: stages 6,7,8 (bits 5,4,3); slots vb + k*8 -----------------
    {
        const unsigned int lo3 = m & 7u, hi = m >> 3;     // hi < 32
        const unsigned int vb  = (hi << 6) | lo3;
        #pragma unroll
        for (int k = 0; k < 8; k++) x[k] = smem[tb + SZ(vb + (k << 3))];
        const unsigned int i   = (__brev(hi) >> 27) << 5; // rev5(hi)<<5
        const unsigned int TA  = shtw[i];
        const unsigned int TB0 = shtw[i >> 1], TB1 = shtw[(i >> 1) + 512u];
        const unsigned int ib  = i >> 2;
        const unsigned int TC0 = shtw[ib],        TC1 = shtw[ib + 512u];
        const unsigned int TC2 = shtw[ib + 256u], TC3 = shtw[ib + 768u];
        bflyT(x[0], x[4], TA); bflyT(x[1], x[5], TA);
        bflyT(x[2], x[6], TA); bflyT(x[3], x[7], TA);
        bflyT(x[0], x[2], TB0); bflyT(x[1], x[3], TB0);
        bflyT(x[4], x[6], TB1); bflyT(x[5], x[7], TB1);
        bflyT(x[0], x[1], TC0); bflyT(x[2], x[3], TC1);
        bflyT(x[4], x[5], TC2); bflyT(x[6], x[7], TC3);
        #pragma unroll
        for (int k = 0; k < 8; k++) smem[tb + SZ(vb + (k << 3))] = x[k];
    }
    barhalf(BAR);

    // ---- R8c: stages 9,10,11 (bits 2,1,0); slots 8m+k -------------------
    {
        #pragma unroll
        for (int k = 0; k < 8; k++) x[k] = smem[tb + SZ(8u * m + k)];
        const unsigned int i   = (__brev(m) >> 24) << 2;  // rev8(m)<<2
        const unsigned int TA  = shtw[i];
        const unsigned int TB0 = shtw[i >> 1], TB1 = shtw[(i >> 1) + 512u];
        const unsigned int ib  = i >> 2;
        const unsigned int TC0 = shtw[ib],        TC1 = shtw[ib + 512u];
        const unsigned int TC2 = shtw[ib + 256u], TC3 = shtw[ib + 768u];
        bflyT(x[0], x[4], TA); bflyT(x[1], x[5], TA);
        bflyT(x[2], x[6], TA); bflyT(x[3], x[7], TA);
        bflyT(x[0], x[2], TB0); bflyT(x[1], x[3], TB0);
        bflyT(x[4], x[6], TB1); bflyT(x[5], x[7], TB1);
        bflyT(x[0], x[1], TC0); bflyT(x[2], x[3], TC1);
        bflyT(x[4], x[5], TC2); bflyT(x[6], x[7], TC3);
        #pragma unroll
        for (int k = 0; k < 8; k++) smem[tb + SZ(8u * m + k)] = x[k];
    }
    __syncthreads();

    // ---- staged store: paired 32B rows into scratch ---------------------
    const unsigned int b0 = __brev(rb0) >> 21;            // < 1024
    const unsigned int b1 = b0 | 1024u;
    #pragma unroll
    for (int rr = 0; rr < 2; rr++) {
        unsigned int p = tid + rr * 512u;                 // < 1024
        size_t base = ((size_t)p << 11);
        g_scratch[(base + b0) * 2 + 0] = smem[SZ(p)];
        g_scratch[(base + b0) * 2 + 1] = smem[SZ(p + 1024u)];
        g_scratch[(base + b1) * 2 + 0] = smem[2048u + SZ(p)];
        g_scratch[(base + b1) * 2 + 1] = smem[2048u + SZ(p + 1024u)];
    }
}

// ---------------------------------------------------------------------------
// Phase 2: stages 12..22 as twisted natural-order 2048-NTT per column.
// Half j owns column C + j*1024 (L = rev11(C)+j); slots s = 8m+k.
// Twist: w^{-L*rev11(s)} * n_inv, rev11(s) = rev8(m) + 256*rev3(k).
// ---------------------------------------------------------------------------
__global__ void __launch_bounds__(512) k_stage2(float4* __restrict__ out,
                                                const unsigned int* __restrict__ tw,
                                                const unsigned int* __restrict__ ni) {
    extern __shared__ uint4 smem[];
    unsigned int* shtw = (unsigned int*)(smem + 4096);

    const unsigned int tid = threadIdx.x;
    const unsigned int C   = blockIdx.x;
    const unsigned int L0  = __brev(C) >> 21;             // even
    const unsigned int j   = tid >> 8, m = tid & 255u;
    const unsigned int tb  = j << 11;
    const unsigned int L   = L0 + j;
    const unsigned int BAR = 1u + j;

    uint4 x[8];
    // ---- prefetch: scratch rows + twist sources (overlap with staging) --
    #pragma unroll
    for (int k = 0; k < 8; k++)
        x[k] = g_scratch[((((size_t)C << 11) + (8u * m + k))) * 2 + j];
    const unsigned int r8m = __brev(m) >> 24;             // rev8(m)
    const unsigned int Fw  = tw[L * r8m];                 // exp < 2^20
    const unsigned int W1s = tw[L << 8];                  // exp < 2^21
    const unsigned int ni0 = ni[0];

    shtw[tid]        = mulmont(tw[(size_t)tid << 11], R2C);
    shtw[tid + 512u] = mulmont(tw[(size_t)(tid + 512u) << 11], R2C);
    __syncthreads();

    // ---- twist + R8a: sg 1,2,3 ------------------------------------------
    {
        const unsigned int X  = mulmont(mulmont(ni0, R2C), R2C);  // ninv * R^2
        const unsigned int Fb = mulmont(Fw, X);
        const unsigned int W1 = mulmont(W1s, R2C);
        const unsigned int W2 = mulmont(W1, W1);
        const unsigned int W3 = mulmont(W2, W1);
        const unsigned int W4 = mulmont(W2, W2);
        const unsigned int W5 = mulmont(W4, W1);
        const unsigned int W6 = mulmont(W3, W3);
        const unsigned int W7 = mulmont(W4, W3);
        unsigned int F[8];                                // Fb * W^{rev3(k)}
        F[0] = Fb;              F[1] = mulmont(Fb, W4);
        F[2] = mulmont(Fb, W2); F[3] = mulmont(Fb, W6);
        F[4] = mulmont(Fb, W1); F[5] = mulmont(Fb, W5);
        F[6] = mulmont(Fb, W3); F[7] = mulmont(Fb, W7);
        #pragma unroll
        for (int k = 0; k < 8; k++) {
            x[k].x = mulmont(x[k].x, F[k]); x[k].y = mulmont(x[k].y, F[k]);
            x[k].z = mulmont(x[k].z, F[k]); x[k].w = mulmont(x[k].w, F[k]);
        }
        const unsigned int J = shtw[512], K1 = shtw[256], K3 = shtw[768];
        bfly1(x[0], x[1]); bfly1(x[2], x[3]); bfly1(x[4], x[5]); bfly1(x[6], x[7]);
        bfly1(x[0], x[2]); bflyT(x[1], x[3], J);
        bfly1(x[4], x[6]); bflyT(x[5], x[7], J);
        bfly1(x[0], x[4]); bflyT(x[1], x[5], K1);
        bflyT(x[2], x[6], J); bflyT(x[3], x[7], K3);
        #pragma unroll
        for (int k = 0; k < 8; k++) smem[tb + SZ(8u * m + k)] = x[k];
    }
    barhalf(BAR);

    // ---- R4: sg 4,5 (strides 8,16); half-local quads q = m, m+256 -------
    #pragma unroll
    for (int r2 = 0; r2 < 2; r2++) {
        unsigned int q   = m + ((unsigned)r2 << 8);       // [0,512)
        unsigned int lo3 = q & 7u, hi = q >> 3;           // hi < 64
        unsigned int h0  = (hi << 5) | lo3;
        unsigned int i   = lo3 << 6;
        unsigned int T4  = shtw[i << 1], T5a = shtw[i], T5b = shtw[i + 512u];
        uint4 x0 = smem[tb + SZ(h0)],        x1 = smem[tb + SZ(h0 + 8u)];
        uint4 x2 = smem[tb + SZ(h0 + 16u)],  x3 = smem[tb + SZ(h0 + 24u)];
        bflyT(x0, x1, T4); bflyT(x2, x3, T4);             // sg=4
        bflyT(x0, x2, T5a); bflyT(x1, x3, T5b);           // sg=5
        smem[tb + SZ(h0)] = x0;        smem[tb + SZ(h0 + 8u)]  = x1;
        smem[tb + SZ(h0 + 16u)] = x2;  smem[tb + SZ(h0 + 24u)] = x3;
    }
    barhalf(BAR);

    // ---- R8b: sg 6,7,8 (strides 32,64,128); slots vb + k*32 -------------
    {
        const unsigned int lo5 = m & 31u, hi = m >> 5;    // hi < 8
        const unsigned int vb  = (hi << 8) | lo5;
        #pragma unroll
        for (int k = 0; k < 8; k++) x[k] = smem[tb + SZ(vb + (k << 5))];
        const unsigned int i   = lo5 << 5;
        const unsigned int TA  = shtw[i];
        const unsigned int TB0 = shtw[i >> 1], TB1 = shtw[(i >> 1) + 512u];
        const unsigned int ib  = i >> 2;
        const unsigned int TC0 = shtw[ib],        TC1 = shtw[ib + 256u];
        const unsigned int TC2 = shtw[ib + 512u], TC3 = shtw[ib + 768u];
        bflyT(x[0], x[1], TA); bflyT(x[2], x[3], TA);
        bflyT(x[4], x[5], TA); bflyT(x[6], x[7], TA);
        bflyT(x[0], x[2], TB0); bflyT(x[1], x[3], TB1);
        bflyT(x[4], x[6], TB0); bflyT(x[5], x[7], TB1);
        bflyT(x[0], x[4], TC0); bflyT(x[1], x[5], TC1);
        bflyT(x[2], x[6], TC2); bflyT(x[3], x[7], TC3);
        #pragma unroll
        for (int k = 0; k < 8; k++) smem[tb + SZ(vb + (k << 5))] = x[k];
    }
    barhalf(BAR);

    // ---- R8c: sg 9,10,11 (strides 256,512,1024); slots k*256+m; fused out
    {
        #pragma unroll
        for (int k = 0; k < 8; k++) x[k] = smem[tb + SZ((k << 8) + m)];
        const unsigned int i   = m << 2;
        const unsigned int TA  = shtw[i];
        const unsigned int TB0 = shtw[i >> 1], TB1 = shtw[(i >> 1) + 512u];
        const unsigned int TC0 = shtw[m],        TC1 = shtw[m + 256u];
        const unsigned int TC2 = shtw[m + 512u], TC3 = shtw[m + 768u];
        bflyT(x[0], x[1], TA); bflyT(x[2], x[3], TA);
        bflyT(x[4], x[5], TA); bflyT(x[6], x[7], TA);
        bflyT(x[0], x[2], TB0); bflyT(x[1], x[3], TB1);
        bflyT(x[4], x[6], TB0); bflyT(x[5], x[7], TB1);
        bflyT(x[0], x[4], TC0); bflyT(x[1], x[5], TC1);
        bflyT(x[2], x[6], TC2); bflyT(x[3], x[7], TC3);
        #pragma unroll
        for (int k = 0; k < 8; k++) {
            size_t row = (((size_t)((k << 8) + m)) << 11) | L;
            out[row] = make_float4((float)x[k].x, (float)x[k].y,
                                   (float)x[k].z, (float)x[k].w);
        }
    }
}

// ---------------------------------------------------------------------------

extern "C" void kernel_launch(void* const* d_in, const int* in_sizes, int n_in,
                              void* d_out, int out_size) {
    const void* p_in = (n_in > 0) ? d_in[0] : nullptr;
    const void* p_tw = (n_in > 1) ? d_in[1] : nullptr;
    const void* p_ni = (n_in > 2) ? d_in[2] : nullptr;
    for (int i = 0; i < n_in; i++) {
        unsigned int sz = (unsigned int)in_sizes[i];
        if (sz == NN * 4u) p_in = d_in[i];
        else if (sz == NH) p_tw = d_in[i];
        else if (sz == 1u) p_ni = d_in[i];
    }

    const int smem = 4096 * (int)sizeof(uint4) + 1024 * (int)sizeof(unsigned int); // 69632
    cudaFuncSetAttribute(k_stage1, cudaFuncAttributeMaxDynamicSharedMemorySize, smem);
    cudaFuncSetAttribute(k_stage2, cudaFuncAttributeMaxDynamicSharedMemorySize, smem);

    k_stage1<<< 1024, 512, smem >>>((const uint4*)p_in, (const unsigned int*)p_tw);
    k_stage2<<< 1024, 512, smem >>>((float4*)d_out, (const unsigned int*)p_tw,
                                    (const unsigned int*)p_ni);
    (void)out_size;
}